// round 11
// baseline (speedup 1.0000x reference)
#include <cuda_runtime.h>
#include <math.h>
#include <stdint.h>

#define Bsz 256
#define Tt  512
#define Hh  512
#define Oo  128
#define MHh 512
#define Ff  256
#define NB  148
#define TPB 512
#define KSC 4      // P3 K-split factor
#define TP  132    // tile smem pitch

// ---------------- device scratch ----------------
__device__ float g_WihI [Oo * 4 * Hh];      // [k][j*4+g]
__device__ float g_WhhI [Hh * 4 * Hh];
__device__ float g_bgI  [4 * Hh];
__device__ float g_Wf2hT[Ff * 2 * Hh];
__device__ float g_bhc  [2 * Hh];
__device__ float g_W12T [Hh * 2 * MHh];     // [k][p1|p2]
__device__ float g_b12  [2 * MHh];
__device__ float g_W2T1 [MHh * Oo];
__device__ float g_W2T2 [MHh * Oo];
__device__ float g_b2cat[2 * Oo];
__device__ float g_offW1T[Hh * MHh];

__device__ float g_hb[2][Bsz * Hh];
__device__ float g_cb[2][Bsz * Hh];
__device__ float g_gp[8][Bsz * 4 * Hh];              // P0 partials (ks_a<=8)
__device__ float g_qp[8][Bsz * MHh];                 // P2 partials (ks_b=8)
__device__ float g_rp[KSC][(size_t)Tt * Bsz * Oo];   // P3 partials per t
__device__ float g_hs [(size_t)Tt * Bsz * Hh];
__device__ float g_buf[(size_t)Tt * Bsz * MHh];
__device__ int   g_nt[Tt];
__device__ unsigned g_barCount;

// ---------------- fast-safe activations (err ~1e-6, threshold 1e-3) ---------
__device__ __forceinline__ float sigm(float x) {
    return __fdividef(1.f, 1.f + __expf(-x));
}
__device__ __forceinline__ float tanh_f(float x) {
    return 1.f - __fdividef(2.f, __expf(2.f * x) + 1.f);
}

// ---------------- preprocessing (2 launches) ----------------
__global__ void k_prepA(const float* __restrict__ W_ih, const float* __restrict__ W_hh,
                        const float* __restrict__ b_ih, const float* __restrict__ b_hh,
                        const float* __restrict__ W_f2h, const float* __restrict__ b_f2h) {
    int i = blockIdx.x * blockDim.x + threadIdx.x;
    if (i < Hh * 4 * Hh) {
        int k = i / 2048, n = i % 2048, j = n >> 2, g = n & 3;
        g_WhhI[i] = W_hh[(size_t)(g * Hh + j) * Hh + k];
    }
    if (i < Oo * 4 * Hh) {
        int k = i / 2048, n = i % 2048, j = n >> 2, g = n & 3;
        g_WihI[i] = W_ih[(size_t)(g * Hh + j) * Oo + k];
    }
    if (i < 4 * Hh) {
        int j = i >> 2, g = i & 3;
        g_bgI[i] = b_ih[g * Hh + j] + b_hh[g * Hh + j];
    }
    if (i < Ff * 2 * Hh) {
        int k = i / (2 * Hh), j = i % (2 * Hh);
        int src = (j < Hh) ? 2 * j : 2 * (j - Hh) + 1;
        g_Wf2hT[i] = W_f2h[(size_t)src * Ff + k];
    }
    if (i < 2 * Hh) {
        int src = (i < Hh) ? 2 * i : 2 * (i - Hh) + 1;
        g_bhc[i] = b_f2h[src];
    }
}

__global__ void k_prepB(const float* __restrict__ p1_W1, const float* __restrict__ p2_W1,
                        const float* __restrict__ p1_b1, const float* __restrict__ p2_b1,
                        const float* __restrict__ p1_W2, const float* __restrict__ p2_W2,
                        const float* __restrict__ p1_b2, const float* __restrict__ p2_b2,
                        const float* __restrict__ off_W1, const int* __restrict__ lengths) {
    int i = blockIdx.x * blockDim.x + threadIdx.x;
    if (i < Hh * 2 * MHh) {
        int k = i / (2 * MHh), n = i % (2 * MHh);
        g_W12T[i] = (n < MHh) ? p1_W1[(size_t)n * Hh + k]
                              : p2_W1[(size_t)(n - MHh) * Hh + k];
    }
    if (i < MHh * Oo) {
        int k = i >> 7, n = i & 127;
        g_W2T1[i] = p1_W2[(size_t)n * MHh + k];
        g_W2T2[i] = p2_W2[(size_t)n * MHh + k];
    }
    if (i < MHh * Hh) {
        int r = i / Hh, c = i % Hh;
        g_offW1T[(size_t)c * MHh + r] = off_W1[i];
    }
    if (i < 2 * MHh) g_b12[i] = (i < MHh) ? p1_b1[i] : p2_b1[i - MHh];
    if (i < 2 * Oo)  g_b2cat[i] = (i < Oo) ? p1_b2[i] : p2_b2[i - Oo];
    if (i == 0) g_barCount = 0u;
    if (i < Tt) {
        int c = 0;
        for (int b = 0; b < Bsz; ++b) c += (lengths[b] > i) ? 1 : 0;
        g_nt[i] = c;
    }
}

// ---------------- 128x128 tile engine, 512 threads, 4x8 micro ----------------
// AF4(m_local, k_local) -> float4 of 4 consecutive k values of row m.
// BF4(k_local, n_local) -> float4 of 4 consecutive n values of row k.
template <class AF4, class BF4>
__device__ __forceinline__ void tile128w(float (&acc)[4][8], int K, AF4 af4, BF4 bf4,
                                         float* As, float* Bs) {
    const int tid = threadIdx.x;
    const int tx = tid & 15, ty = tid >> 4;     // ty 0..31
    const int la_k = (tid & 3) * 4;             // A: k offset
    const int la_m = tid >> 2;                  // A: m 0..127
    const int lb_n = (tid & 31) * 4;            // B: n offset
    const int lb_r = tid >> 5;                  // B: k row 0..15

    float4 pa = af4(la_m, la_k);
    float4 pb = bf4(lb_r, lb_n);

    for (int kt = 0; kt < K; kt += 16) {
        float* ap = &As[la_k * TP + la_m];
        ap[0] = pa.x; ap[TP] = pa.y; ap[2 * TP] = pa.z; ap[3 * TP] = pa.w;
        *(float4*)&Bs[lb_r * TP + lb_n] = pb;
        __syncthreads();
        if (kt + 16 < K) {
            pa = af4(la_m, kt + 16 + la_k);
            pb = bf4(kt + 16 + lb_r, lb_n);
        }
#pragma unroll
        for (int k = 0; k < 16; ++k) {
            float4 a = *(const float4*)&As[k * TP + ty * 4];
            float4 b0 = *(const float4*)&Bs[k * TP + tx * 4];
            float4 b1 = *(const float4*)&Bs[k * TP + 64 + tx * 4];
            float av[4] = {a.x, a.y, a.z, a.w};
            float bv[8] = {b0.x, b0.y, b0.z, b0.w, b1.x, b1.y, b1.z, b1.w};
#pragma unroll
            for (int i = 0; i < 4; ++i)
#pragma unroll
                for (int j = 0; j < 8; ++j)
                    acc[i][j] += av[i] * bv[j];
        }
        __syncthreads();
    }
}

// epilogue n index: j<4 -> n0+tx*4+j ; j>=4 -> n0+64+tx*4+j-4
__device__ __forceinline__ int tile_n(int n0, int tx, int j) {
    return n0 + ((j < 4) ? (tx * 4 + j) : (64 + tx * 4 + (j - 4)));
}

// ---------------- generic GEMM on tile128w ----------------
// MODE 0: C=acc+bias ; 1: tanh ; 2: h/c split init
template <int MODE>
__global__ void __launch_bounds__(TPB, 1)
gemmG(const float* __restrict__ A, int lda, const int* __restrict__ aidx,
      const float* __restrict__ Bm, int ldb, const float* __restrict__ bias,
      float* __restrict__ C, int M, int N, int K) {
    __shared__ __align__(16) float As[16 * TP];
    __shared__ __align__(16) float Bs[16 * TP];
    const int n0 = blockIdx.x * 128;
    const int m0 = blockIdx.y * 128;
    const int tx = threadIdx.x & 15, ty = threadIdx.x >> 4;

    float acc[4][8] = {};

    auto af4 = [&](int ml, int kk) -> float4 {
        int m = m0 + ml;
        if (m >= M) return make_float4(0.f, 0.f, 0.f, 0.f);
        int row = aidx ? aidx[m] : m;
        return *(const float4*)&A[(size_t)row * lda + kk];
    };
    auto bf4 = [&](int kk, int nl) -> float4 {
        return *(const float4*)&Bm[(size_t)kk * ldb + n0 + nl];
    };
    tile128w(acc, K, af4, bf4, As, Bs);

#pragma unroll
    for (int i = 0; i < 4; ++i) {
        int m = m0 + ty * 4 + i;
        if (m >= M) continue;
#pragma unroll
        for (int j = 0; j < 8; ++j) {
            int n = tile_n(n0, tx, j);
            float r = acc[i][j] + (bias ? bias[n] : 0.f);
            if (MODE == 1) r = tanh_f(r);
            if (MODE == 2) {
                if (n < Hh) g_hb[0][m * Hh + n] = r;
                else        g_cb[0][m * Hh + (n - Hh)] = r;
            } else {
                C[(size_t)m * N + n] = r;
            }
        }
    }
}

// ---------------- persistent scan ----------------
__device__ __forceinline__ void gridsync(unsigned& phase) {
    __syncthreads();
    if (threadIdx.x == 0) {
        __threadfence();
        phase += 1u;
        const unsigned target = phase * NB;
        atomicAdd(&g_barCount, 1u);
        while (*((volatile unsigned*)&g_barCount) < target) {}
        __threadfence();
    }
    __syncthreads();
}

__global__ void __launch_bounds__(TPB, 1) persistent_scan() {
    __shared__ __align__(16) float As[16 * TP];
    __shared__ __align__(16) float Bs[16 * TP];
    const int bid = blockIdx.x;
    const int tid = threadIdx.x;
    const int tx = tid & 15, ty = tid >> 4;
    unsigned phase = 0;

    for (int t = 0; t < Tt; ++t) {
        const int nt = g_nt[t];
        const int m128 = (nt + 127) >> 7;
        const int rd = t & 1, wr = rd ^ 1;
        const float* __restrict__ hR = g_hb[rd];
        float* __restrict__ hW = g_hb[wr];
        const float* __restrict__ cR = g_cb[rd];
        float* __restrict__ cW = g_cb[wr];
        const bool hasx = (t > 0);
        const int xoff = hasx ? 128 : 0;
        const int kspace = Hh + xoff;                  // 640 or 512
        const int ks_a = (m128 == 2) ? 4 : 8;
        const int Ka = kspace / ks_a;                  // 160/128 or 80/64
        const size_t rbase = hasx ? (size_t)(t - 1) * Bsz * Oo : 0;

        // ---- P0: gates partials = x@WihI + h@WhhI (tile128w, K-split) ----
        const int tilesA = m128 * 16 * ks_a;
        for (int tile = bid; tile < tilesA; tile += NB) {
            const int s  = tile % ks_a;
            const int u  = tile / ks_a;
            const int n0 = (u & 15) << 7;
            const int m0 = (u >> 4) << 7;
            const int k0 = s * Ka;

            float acc[4][8] = {};
            auto af4 = [&](int ml, int kk) -> float4 {
                int gk = k0 + kk;
                int m = m0 + ml;
                if (hasx && gk < Oo) {
                    size_t ix = rbase + (size_t)m * Oo + gk;
                    float4 v = *(const float4*)&g_b2cat[gk];
#pragma unroll
                    for (int sc = 0; sc < KSC; ++sc) {
                        float4 r = *(const float4*)&g_rp[sc][ix];
                        v.x += r.x; v.y += r.y; v.z += r.z; v.w += r.w;
                    }
                    return v;
                }
                return *(const float4*)&hR[m * Hh + gk - xoff];
            };
            auto bf4 = [&](int kk, int nl) -> float4 {
                int gk = k0 + kk;
                const float* src = (hasx && gk < Oo)
                    ? &g_WihI[gk * 2048 + n0 + nl]
                    : &g_WhhI[(size_t)(gk - xoff) * 2048 + n0 + nl];
                return *(const float4*)src;
            };
            tile128w(acc, Ka, af4, bf4, As, Bs);

            float* __restrict__ gout = g_gp[s];
#pragma unroll
            for (int i = 0; i < 4; ++i) {
                float* dst = &gout[(m0 + ty * 4 + i) * 2048 + n0];
                *(float4*)&dst[tx * 4] =
                    make_float4(acc[i][0], acc[i][1], acc[i][2], acc[i][3]);
                *(float4*)&dst[64 + tx * 4] =
                    make_float4(acc[i][4], acc[i][5], acc[i][6], acc[i][7]);
            }
        }
        gridsync(phase);

        // ---- P1: LSTM combine (sum ks_a partials + bias) ----
        {
            const int total = m128 * 128 * Hh;
            for (int e = bid * TPB + tid; e < total; e += NB * TPB) {
                int m = e >> 9, j = e & (Hh - 1);
                if (m < nt) {
                    float4 gs = make_float4(0.f, 0.f, 0.f, 0.f);
                    for (int s = 0; s < ks_a; ++s) {
                        float4 gp = *(const float4*)&g_gp[s][m * 2048 + j * 4];
                        gs.x += gp.x; gs.y += gp.y; gs.z += gp.z; gs.w += gp.w;
                    }
                    float4 bg = *(const float4*)&g_bgI[j * 4];
                    float cn = sigm(gs.y + bg.y) * cR[m * Hh + j] +
                               sigm(gs.x + bg.x) * tanh_f(gs.z + bg.z);
                    float hn = sigm(gs.w + bg.w) * tanh_f(cn);
                    cW[m * Hh + j] = cn;
                    hW[m * Hh + j] = hn;
                    g_hs[((size_t)t * Bsz + m) * Hh + j] = hn;
                }
            }
            gridsync(phase);
        }

        // ---- P2: q partials = h_t @ W12T[:, 0:512], K-split 8 ----
        const int Kb = MHh / 8;   // 64
        const int tilesB = m128 * 4 * 8;
        for (int tile = bid; tile < tilesB; tile += NB) {
            const int s  = tile & 7;
            const int u  = tile >> 3;
            const int n0 = (u & 3) << 7;
            const int m0 = (u >> 2) << 7;
            const int k0 = s * Kb;

            float acc[4][8] = {};
            auto af4 = [&](int ml, int kk) -> float4 {
                return *(const float4*)&hW[(m0 + ml) * Hh + k0 + kk];
            };
            auto bf4 = [&](int kk, int nl) -> float4 {
                return *(const float4*)&g_W12T[(size_t)(k0 + kk) * 1024 + n0 + nl];
            };
            tile128w(acc, Kb, af4, bf4, As, Bs);

            float* __restrict__ qout = g_qp[s];
#pragma unroll
            for (int i = 0; i < 4; ++i) {
                float* dst = &qout[(m0 + ty * 4 + i) * MHh + n0];
                *(float4*)&dst[tx * 4] =
                    make_float4(acc[i][0], acc[i][1], acc[i][2], acc[i][3]);
                *(float4*)&dst[64 + tx * 4] =
                    make_float4(acc[i][4], acc[i][5], acc[i][6], acc[i][7]);
            }
        }
        gridsync(phase);

        // ---- P3: p1 partials = tanh(sum q + b12) @ W2T1, K-split 4 ----
        const int Kc = MHh / KSC;    // 128
        const int tilesC = m128 * KSC;
        for (int tile = bid; tile < tilesC; tile += NB) {
            const int s  = tile % KSC;
            const int m0 = (tile / KSC) << 7;
            const int k0 = s * Kc;
            float* __restrict__ rout = g_rp[s] + (size_t)t * Bsz * Oo;

            float acc[4][8] = {};
            auto af4 = [&](int ml, int kk) -> float4 {
                int k = k0 + kk;
                int m = m0 + ml;
                float4 v = *(const float4*)&g_b12[k];
#pragma unroll
                for (int s2 = 0; s2 < 8; ++s2) {
                    float4 q = *(const float4*)&g_qp[s2][m * MHh + k];
                    v.x += q.x; v.y += q.y; v.z += q.z; v.w += q.w;
                }
                return make_float4(tanh_f(v.x), tanh_f(v.y), tanh_f(v.z), tanh_f(v.w));
            };
            auto bf4 = [&](int kk, int nl) -> float4 {
                return *(const float4*)&g_W2T1[(k0 + kk) * Oo + nl];
            };
            tile128w(acc, Kc, af4, bf4, As, Bs);

#pragma unroll
            for (int i = 0; i < 4; ++i) {
                float* dst = &rout[(size_t)(m0 + ty * 4 + i) * Oo];
                *(float4*)&dst[tx * 4] =
                    make_float4(acc[i][0], acc[i][1], acc[i][2], acc[i][3]);
                *(float4*)&dst[64 + tx * 4] =
                    make_float4(acc[i][4], acc[i][5], acc[i][6], acc[i][7]);
            }
        }
        gridsync(phase);
    }
}

// ---------------- final stage ----------------
__global__ void offsets_kernel(const float* __restrict__ offW2, const float* __restrict__ offb2,
                               float* __restrict__ out_off, int Np) {
    int warp = (blockIdx.x * blockDim.x + threadIdx.x) >> 5;
    int lane = threadIdx.x & 31;
    if (warp >= Np) return;
    const float* row = g_buf + (size_t)warp * MHh;
    float s = 0.f;
#pragma unroll
    for (int k = lane; k < MHh; k += 32) s += row[k] * offW2[k];
#pragma unroll
    for (int o = 16; o; o >>= 1) s += __shfl_xor_sync(0xFFFFFFFFu, s, o);
    if (lane == 0) out_off[warp] = s + offb2[0];
}

__global__ void gather_out(const int* __restrict__ pack_idx, float* __restrict__ out, int Np) {
    int gid = blockIdx.x * blockDim.x + threadIdx.x;
    if (gid >= Np * Oo) return;
    int i = gid >> 7, o = gid & 127;
    size_t p = (size_t)pack_idx[i];
    float v1 = g_b2cat[o];
#pragma unroll
    for (int s = 0; s < KSC; ++s) v1 += g_rp[s][p * Oo + o];
    size_t NO = (size_t)Np * Oo;
    out[(size_t)i * Oo + o] = v1;                 // flat_p1
    out[2 * NO + Np + (size_t)i * Oo + o] = v1;   // flat_out (== flat_p1)
}

// ---------------- host ----------------
static float* gsymf(const void* symbol) {
    void* p = nullptr;
    cudaGetSymbolAddress(&p, symbol);
    return (float*)p;
}

extern "C" void kernel_launch(void* const* d_in, const int* in_sizes, int n_in,
                              void* d_out, int out_size) {
    const float* features = (const float*)d_in[0];
    const float* W_f2h    = (const float*)d_in[1];
    const float* b_f2h    = (const float*)d_in[2];
    const float* W_ih     = (const float*)d_in[3];
    const float* W_hh     = (const float*)d_in[4];
    const float* b_ih     = (const float*)d_in[5];
    const float* b_hh     = (const float*)d_in[6];
    const float* p1_W1    = (const float*)d_in[7];
    const float* p1_b1    = (const float*)d_in[8];
    const float* p1_W2    = (const float*)d_in[9];
    const float* p1_b2    = (const float*)d_in[10];
    const float* p2_W1    = (const float*)d_in[11];
    const float* p2_b1    = (const float*)d_in[12];
    const float* p2_W2    = (const float*)d_in[13];
    const float* p2_b2    = (const float*)d_in[14];
    const float* off_W1   = (const float*)d_in[15];
    const float* off_b1   = (const float*)d_in[16];
    const float* off_W2   = (const float*)d_in[17];
    const float* off_b2   = (const float*)d_in[18];
    const int*   lengths  = (const int*)d_in[19];
    const int*   pack_idx = (const int*)d_in[20];
    float* out = (float*)d_out;
    const int Np = in_sizes[20];
    const size_t NO = (size_t)Np * Oo;
    const unsigned mT = (unsigned)((Np + 127) / 128);

    float* p_Wf2hT  = gsymf(g_Wf2hT);
    float* p_bhc    = gsymf(g_bhc);
    float* p_W12T   = gsymf(g_W12T);
    float* p_b12    = gsymf(g_b12);
    float* p_W2T2   = gsymf(g_W2T2);
    float* p_b2cat  = gsymf(g_b2cat);
    float* p_offW1T = gsymf(g_offW1T);
    float* p_hs     = gsymf(g_hs);
    float* p_buf    = gsymf(g_buf);

    auto blocks = [](long long n) { return (unsigned)((n + 255) / 256); };

    // launch 1-2: prep ; launch 3: init GEMM ; launch 4: the scan
    k_prepA<<<blocks(4LL * Hh * Hh), 256>>>(W_ih, W_hh, b_ih, b_hh, W_f2h, b_f2h);
    k_prepB<<<blocks((long long)Hh * 2 * MHh), 256>>>(p1_W1, p2_W1, p1_b1, p2_b1,
                                                      p1_W2, p2_W2, p1_b2, p2_b2,
                                                      off_W1, lengths);
    gemmG<2><<<dim3(8, 2), TPB>>>(features, Ff, nullptr, p_Wf2hT, 2 * Hh, p_bhc,
                                  nullptr, Bsz, 2 * Hh, Ff);
    persistent_scan<<<NB, TPB>>>();

    // post-loop over packed rows
    gemmG<1><<<dim3(4, mT), TPB>>>(p_hs, Hh, pack_idx, p_offW1T, MHh, off_b1,
                                   p_buf, Np, MHh, Hh);
    offsets_kernel<<<(Np + 7) / 8, 256>>>(off_W2, off_b2, out + 2 * NO, Np);

    gemmG<1><<<dim3(4, mT), TPB>>>(p_hs, Hh, pack_idx, p_W12T + MHh, 2 * MHh, p_b12 + MHh,
                                   p_buf, Np, MHh, Hh);
    gemmG<0><<<dim3(1, mT), TPB>>>(p_buf, MHh, nullptr, p_W2T2, Oo, p_b2cat + Oo,
                                   out + NO, Np, Oo, MHh);

    gather_out<<<blocks((long long)Np * Oo), 256>>>(pack_idx, out, Np);
}

// round 12
// speedup vs baseline: 1.2606x; 1.2606x over previous
#include <cuda_runtime.h>
#include <math.h>
#include <stdint.h>

#define Bsz 256
#define Tt  512
#define Hh  512
#define Oo  128
#define MHh 512
#define Ff  256
#define NB  148
#define TPB 256
#define KSC 4      // P3 K-split factor
#define PAP 68     // mac64 A-tile pitch
#define TP  132    // tile128 smem pitch
#define BUFO (16 * TP)   // double-buffer offset (floats)

// ---------------- device scratch ----------------
__device__ float g_WihI [Oo * 4 * Hh];      // [k][j*4+g]
__device__ float g_WhhI [Hh * 4 * Hh];
__device__ float g_bgI  [4 * Hh];
__device__ float g_Wf2hT[Ff * 2 * Hh];
__device__ float g_bhc  [2 * Hh];
__device__ float g_W12T [Hh * 2 * MHh];     // [k][p1|p2]
__device__ float g_b12  [2 * MHh];
__device__ float g_W2T1 [MHh * Oo];
__device__ float g_W2T2 [MHh * Oo];
__device__ float g_b2cat[2 * Oo];
__device__ float g_offW1T[Hh * MHh];

__device__ float g_hb[2][Bsz * Hh];
__device__ float g_cb[2][Bsz * Hh];
__device__ float g_gp[8][Bsz * 4 * Hh];              // P0 partials (ks_a<=8)
__device__ float g_qp[8][Bsz * MHh];                 // P2 partials (ks_b=8)
__device__ float g_rp[KSC][(size_t)Tt * Bsz * Oo];   // P3 partials per t
__device__ float g_hs [(size_t)Tt * Bsz * Hh];
__device__ float g_buf[(size_t)Tt * Bsz * MHh];
__device__ int   g_nt[Tt];
__device__ unsigned g_barCount;

// ---------------- fast-safe activations (err ~1e-6, threshold 1e-3) ---------
__device__ __forceinline__ float sigm(float x) {
    return __fdividef(1.f, 1.f + __expf(-x));
}
__device__ __forceinline__ float tanh_f(float x) {
    return 1.f - __fdividef(2.f, __expf(2.f * x) + 1.f);
}

// ---------------- preprocessing (2 launches) ----------------
__global__ void k_prepA(const float* __restrict__ W_ih, const float* __restrict__ W_hh,
                        const float* __restrict__ b_ih, const float* __restrict__ b_hh,
                        const float* __restrict__ W_f2h, const float* __restrict__ b_f2h) {
    int i = blockIdx.x * blockDim.x + threadIdx.x;
    if (i < Hh * 4 * Hh) {
        int k = i / 2048, n = i % 2048, j = n >> 2, g = n & 3;
        g_WhhI[i] = W_hh[(size_t)(g * Hh + j) * Hh + k];
    }
    if (i < Oo * 4 * Hh) {
        int k = i / 2048, n = i % 2048, j = n >> 2, g = n & 3;
        g_WihI[i] = W_ih[(size_t)(g * Hh + j) * Oo + k];
    }
    if (i < 4 * Hh) {
        int j = i >> 2, g = i & 3;
        g_bgI[i] = b_ih[g * Hh + j] + b_hh[g * Hh + j];
    }
    if (i < Ff * 2 * Hh) {
        int k = i / (2 * Hh), j = i % (2 * Hh);
        int src = (j < Hh) ? 2 * j : 2 * (j - Hh) + 1;
        g_Wf2hT[i] = W_f2h[(size_t)src * Ff + k];
    }
    if (i < 2 * Hh) {
        int src = (i < Hh) ? 2 * i : 2 * (i - Hh) + 1;
        g_bhc[i] = b_f2h[src];
    }
}

__global__ void k_prepB(const float* __restrict__ p1_W1, const float* __restrict__ p2_W1,
                        const float* __restrict__ p1_b1, const float* __restrict__ p2_b1,
                        const float* __restrict__ p1_W2, const float* __restrict__ p2_W2,
                        const float* __restrict__ p1_b2, const float* __restrict__ p2_b2,
                        const float* __restrict__ off_W1, const int* __restrict__ lengths) {
    int i = blockIdx.x * blockDim.x + threadIdx.x;
    if (i < Hh * 2 * MHh) {
        int k = i / (2 * MHh), n = i % (2 * MHh);
        g_W12T[i] = (n < MHh) ? p1_W1[(size_t)n * Hh + k]
                              : p2_W1[(size_t)(n - MHh) * Hh + k];
    }
    if (i < MHh * Oo) {
        int k = i >> 7, n = i & 127;
        g_W2T1[i] = p1_W2[(size_t)n * MHh + k];
        g_W2T2[i] = p2_W2[(size_t)n * MHh + k];
    }
    if (i < MHh * Hh) {
        int r = i / Hh, c = i % Hh;
        g_offW1T[(size_t)c * MHh + r] = off_W1[i];
    }
    if (i < 2 * MHh) g_b12[i] = (i < MHh) ? p1_b1[i] : p2_b1[i - MHh];
    if (i < 2 * Oo)  g_b2cat[i] = (i < Oo) ? p1_b2[i] : p2_b2[i - Oo];
    if (i == 0) g_barCount = 0u;
    if (i < Tt) {
        int c = 0;
        for (int b = 0; b < Bsz; ++b) c += (lengths[b] > i) ? 1 : 0;
        g_nt[i] = c;
    }
}

// ---------------- 128x128 tile engine (8x8 micro, double-buffered) ----------
// As/Bs arrays hold TWO buffers, BUFO floats apart.
template <class AF4, class BF4>
__device__ __forceinline__ void tile128(float (&acc)[2][2][4][4], int K, AF4 af4, BF4 bf4,
                                        float* As, float* Bs) {
    const int tid = threadIdx.x;
    const int tx = tid & 15, ty = tid >> 4;
    const int la_k = (tid & 3) * 4;
    const int la_m = tid >> 2;
    const int lb_n = (tid & 31) * 4;
    const int lb_r = tid >> 5;

    float4 pa0 = af4(la_m, la_k);
    float4 pa1 = af4(la_m + 64, la_k);
    float4 pb0 = bf4(lb_r, lb_n);
    float4 pb1 = bf4(lb_r + 8, lb_n);

    __syncthreads();   // protect smem from previous call's readers
    {
        float* a0p = &As[la_k * TP + la_m];
        a0p[0] = pa0.x; a0p[TP] = pa0.y; a0p[2 * TP] = pa0.z; a0p[3 * TP] = pa0.w;
        float* a1p = a0p + 64;
        a1p[0] = pa1.x; a1p[TP] = pa1.y; a1p[2 * TP] = pa1.z; a1p[3 * TP] = pa1.w;
        *(float4*)&Bs[lb_r * TP + lb_n] = pb0;
        *(float4*)&Bs[(lb_r + 8) * TP + lb_n] = pb1;
    }
    __syncthreads();

    const int nch = K >> 4;
    for (int c = 0; c < nch; ++c) {
        float* Ac = As + (c & 1) * BUFO;
        float* Bc = Bs + (c & 1) * BUFO;
        const bool more = (c + 1 < nch);
        if (more) {
            const int k1 = (c + 1) << 4;
            pa0 = af4(la_m, k1 + la_k);
            pa1 = af4(la_m + 64, k1 + la_k);
            pb0 = bf4(k1 + lb_r, lb_n);
            pb1 = bf4(k1 + lb_r + 8, lb_n);
        }
#pragma unroll
        for (int k = 0; k < 16; ++k) {
            float4 a0 = *(const float4*)&Ac[k * TP + ty * 4];
            float4 a1 = *(const float4*)&Ac[k * TP + 64 + ty * 4];
            float4 b0 = *(const float4*)&Bc[k * TP + tx * 4];
            float4 b1 = *(const float4*)&Bc[k * TP + 64 + tx * 4];
            float av[2][4] = {{a0.x, a0.y, a0.z, a0.w}, {a1.x, a1.y, a1.z, a1.w}};
            float bv[2][4] = {{b0.x, b0.y, b0.z, b0.w}, {b1.x, b1.y, b1.z, b1.w}};
#pragma unroll
            for (int ih = 0; ih < 2; ++ih)
#pragma unroll
                for (int jh = 0; jh < 2; ++jh)
#pragma unroll
                    for (int i = 0; i < 4; ++i)
#pragma unroll
                        for (int j = 0; j < 4; ++j)
                            acc[ih][jh][i][j] += av[ih][i] * bv[jh][j];
        }
        if (more) {
            float* An = As + ((c + 1) & 1) * BUFO;
            float* Bn = Bs + ((c + 1) & 1) * BUFO;
            float* a0p = &An[la_k * TP + la_m];
            a0p[0] = pa0.x; a0p[TP] = pa0.y; a0p[2 * TP] = pa0.z; a0p[3 * TP] = pa0.w;
            float* a1p = a0p + 64;
            a1p[0] = pa1.x; a1p[TP] = pa1.y; a1p[2 * TP] = pa1.z; a1p[3 * TP] = pa1.w;
            *(float4*)&Bn[lb_r * TP + lb_n] = pb0;
            *(float4*)&Bn[(lb_r + 8) * TP + lb_n] = pb1;
            __syncthreads();
        }
    }
}

// ---------------- 64x64 MAC core (double-buffered) ----------------
template <class AF, class BF>
__device__ __forceinline__ void mac64(float (&acc)[4][4], int K, AF af, BF bf,
                                      float* As, float* Bs) {
    const int tid = threadIdx.x;
    const int tx = tid & 15, ty = tid >> 4;
    const int bk = tid >> 6, bn = tid & 63;
    float ra[4], rb[4];
#pragma unroll
    for (int i = 0; i < 4; ++i) ra[i] = af(ty * 4 + i, tx);
#pragma unroll
    for (int i = 0; i < 4; ++i) rb[i] = bf(bk + i * 4, bn);

    __syncthreads();   // protect smem from previous call's readers
    *(float4*)&As[tx * PAP + ty * 4] = make_float4(ra[0], ra[1], ra[2], ra[3]);
#pragma unroll
    for (int i = 0; i < 4; ++i) Bs[(bk + i * 4) * 64 + bn] = rb[i];
    __syncthreads();

    const int nch = K >> 4;
    for (int c = 0; c < nch; ++c) {
        float* Ac = As + (c & 1) * BUFO;
        float* Bc = Bs + (c & 1) * BUFO;
        const bool more = (c + 1 < nch);
        if (more) {
            const int k1 = (c + 1) << 4;
#pragma unroll
            for (int i = 0; i < 4; ++i) ra[i] = af(ty * 4 + i, k1 + tx);
#pragma unroll
            for (int i = 0; i < 4; ++i) rb[i] = bf(k1 + bk + i * 4, bn);
        }
#pragma unroll
        for (int k = 0; k < 16; ++k) {
            float4 a4 = *(const float4*)&Ac[k * PAP + ty * 4];
            float4 b4 = *(const float4*)&Bc[k * 64 + tx * 4];
            float av[4] = {a4.x, a4.y, a4.z, a4.w};
            float bv[4] = {b4.x, b4.y, b4.z, b4.w};
#pragma unroll
            for (int i = 0; i < 4; ++i)
#pragma unroll
                for (int j = 0; j < 4; ++j) acc[i][j] += av[i] * bv[j];
        }
        if (more) {
            float* An = As + ((c + 1) & 1) * BUFO;
            float* Bn = Bs + ((c + 1) & 1) * BUFO;
            *(float4*)&An[tx * PAP + ty * 4] = make_float4(ra[0], ra[1], ra[2], ra[3]);
#pragma unroll
            for (int i = 0; i < 4; ++i) Bn[(bk + i * 4) * 64 + bn] = rb[i];
            __syncthreads();
        }
    }
}

// ---------------- generic GEMM on tile128 ----------------
// MODE 0: C=acc+bias ; 1: tanh ; 2: h/c split init
template <int MODE>
__global__ void __launch_bounds__(256)
gemmG(const float* __restrict__ A, int lda, const int* __restrict__ aidx,
      const float* __restrict__ Bm, int ldb, const float* __restrict__ bias,
      float* __restrict__ C, int M, int N, int K) {
    __shared__ __align__(16) float As[2 * BUFO];
    __shared__ __align__(16) float Bs[2 * BUFO];
    const int n0 = blockIdx.x * 128;
    const int m0 = blockIdx.y * 128;
    const int tx = threadIdx.x & 15, ty = threadIdx.x >> 4;

    float acc[2][2][4][4] = {};

    auto af4 = [&](int ml, int kk) -> float4 {
        int m = m0 + ml;
        if (m >= M) return make_float4(0.f, 0.f, 0.f, 0.f);
        int row = aidx ? aidx[m] : m;
        return *(const float4*)&A[(size_t)row * lda + kk];
    };
    auto bf4 = [&](int kk, int nl) -> float4 {
        return *(const float4*)&Bm[(size_t)kk * ldb + n0 + nl];
    };
    tile128(acc, K, af4, bf4, As, Bs);

#pragma unroll
    for (int ih = 0; ih < 2; ++ih)
#pragma unroll
        for (int i = 0; i < 4; ++i) {
            int m = m0 + ih * 64 + ty * 4 + i;
            if (m >= M) continue;
#pragma unroll
            for (int jh = 0; jh < 2; ++jh)
#pragma unroll
                for (int j = 0; j < 4; ++j) {
                    int n = n0 + jh * 64 + tx * 4 + j;
                    float r = acc[ih][jh][i][j] + (bias ? bias[n] : 0.f);
                    if (MODE == 1) r = tanh_f(r);
                    if (MODE == 2) {
                        if (n < Hh) g_hb[0][m * Hh + n] = r;
                        else        g_cb[0][m * Hh + (n - Hh)] = r;
                    } else {
                        C[(size_t)m * N + n] = r;
                    }
                }
        }
}

// ---------------- persistent scan ----------------
__device__ __forceinline__ void gridsync(unsigned& phase) {
    __syncthreads();
    if (threadIdx.x == 0) {
        __threadfence();
        phase += 1u;
        const unsigned target = phase * NB;
        atomicAdd(&g_barCount, 1u);
        while (*((volatile unsigned*)&g_barCount) < target) {}
        __threadfence();
    }
    __syncthreads();
}

__global__ void __launch_bounds__(TPB, 1) persistent_scan() {
    __shared__ __align__(16) float As[2 * BUFO];
    __shared__ __align__(16) float Bs[2 * BUFO];
    const int bid = blockIdx.x;
    const int tid = threadIdx.x;
    const int tx = tid & 15, ty = tid >> 4;
    unsigned phase = 0;

    for (int t = 0; t < Tt; ++t) {
        const int nt = g_nt[t];
        const int mt   = (nt + 63) >> 6;
        const int m128 = (nt + 127) >> 7;
        const int rd = t & 1, wr = rd ^ 1;
        const float* __restrict__ hR = g_hb[rd];
        float* __restrict__ hW = g_hb[wr];
        const float* __restrict__ cR = g_cb[rd];
        float* __restrict__ cW = g_cb[wr];
        const bool hasx = (t > 0);
        const int xoff = hasx ? 128 : 0;
        const int kspace = Hh + xoff;                  // 640 or 512
        const bool small = (nt <= 64);                 // 64-row P0 path
        const int ks_a = small ? 4 : ((m128 == 2) ? 4 : 8);
        const int Ka = kspace / ks_a;
        const size_t rbase = hasx ? (size_t)(t - 1) * Bsz * Oo : 0;

        // A-operand scalar loader (shared by both P0 paths)
        auto afs = [&](int m, int gk) -> float {
            if (hasx && gk < Oo) {
                size_t ix = rbase + (size_t)m * Oo + gk;
                float v = g_b2cat[gk];
#pragma unroll
                for (int sc = 0; sc < KSC; ++sc) v += g_rp[sc][ix];
                return v;
            }
            return hR[m * Hh + gk - xoff];
        };

        // ---- P0: gates partials = x@WihI + h@WhhI ----
        if (small) {
            const int tilesA = 32 * ks_a;
            for (int tile = bid; tile < tilesA; tile += NB) {
                const int s  = tile % ks_a;
                const int n0 = (tile / ks_a) << 6;
                const int k0 = s * Ka;
                float acc[4][4] = {};
                auto af = [&](int ml, int kk) -> float { return afs(ml, k0 + kk); };
                auto bf = [&](int kk, int nl) -> float {
                    int gk = k0 + kk;
                    return (hasx && gk < Oo) ? g_WihI[gk * 2048 + n0 + nl]
                                             : g_WhhI[(size_t)(gk - xoff) * 2048 + n0 + nl];
                };
                mac64(acc, Ka, af, bf, As, Bs);
                float* __restrict__ gout = g_gp[s];
#pragma unroll
                for (int i = 0; i < 4; ++i) {
                    int m = ty * 4 + i;
#pragma unroll
                    for (int j = 0; j < 4; ++j)
                        gout[m * 2048 + n0 + tx * 4 + j] = acc[i][j];
                }
            }
        } else {
            const int tilesA = m128 * 16 * ks_a;
            for (int tile = bid; tile < tilesA; tile += NB) {
                const int s  = tile % ks_a;
                const int u  = tile / ks_a;
                const int n0 = (u & 15) << 7;
                const int m0 = (u >> 4) << 7;
                const int k0 = s * Ka;

                float acc[2][2][4][4] = {};
                auto af4 = [&](int ml, int kk) -> float4 {
                    int gk = k0 + kk;
                    int m = m0 + ml;
                    if (hasx && gk < Oo) {
                        size_t ix = rbase + (size_t)m * Oo + gk;
                        float4 v = *(const float4*)&g_b2cat[gk];
#pragma unroll
                        for (int sc = 0; sc < KSC; ++sc) {
                            float4 r = *(const float4*)&g_rp[sc][ix];
                            v.x += r.x; v.y += r.y; v.z += r.z; v.w += r.w;
                        }
                        return v;
                    }
                    return *(const float4*)&hR[m * Hh + gk - xoff];
                };
                auto bf4 = [&](int kk, int nl) -> float4 {
                    int gk = k0 + kk;
                    const float* src = (hasx && gk < Oo)
                        ? &g_WihI[gk * 2048 + n0 + nl]
                        : &g_WhhI[(size_t)(gk - xoff) * 2048 + n0 + nl];
                    return *(const float4*)src;
                };
                tile128(acc, Ka, af4, bf4, As, Bs);

                float* __restrict__ gout = g_gp[s];
#pragma unroll
                for (int ih = 0; ih < 2; ++ih)
#pragma unroll
                    for (int i = 0; i < 4; ++i) {
                        int m = m0 + ih * 64 + ty * 4 + i;
                        float* dst = &gout[m * 2048 + n0];
#pragma unroll
                        for (int jh = 0; jh < 2; ++jh)
                            *(float4*)&dst[jh * 64 + tx * 4] =
                                make_float4(acc[ih][jh][i][0], acc[ih][jh][i][1],
                                            acc[ih][jh][i][2], acc[ih][jh][i][3]);
                    }
            }
        }
        gridsync(phase);

        // ---- P1: LSTM combine (sum ks_a partials + bias) ----
        {
            const int total = mt * 64 * Hh;
            for (int e = bid * TPB + tid; e < total; e += NB * TPB) {
                int m = e >> 9, j = e & (Hh - 1);
                if (m < nt) {
                    float4 gs = make_float4(0.f, 0.f, 0.f, 0.f);
                    for (int s = 0; s < ks_a; ++s) {
                        float4 gp = *(const float4*)&g_gp[s][m * 2048 + j * 4];
                        gs.x += gp.x; gs.y += gp.y; gs.z += gp.z; gs.w += gp.w;
                    }
                    float4 bg = *(const float4*)&g_bgI[j * 4];
                    float cn = sigm(gs.y + bg.y) * cR[m * Hh + j] +
                               sigm(gs.x + bg.x) * tanh_f(gs.z + bg.z);
                    float hn = sigm(gs.w + bg.w) * tanh_f(cn);
                    cW[m * Hh + j] = cn;
                    hW[m * Hh + j] = hn;
                    g_hs[((size_t)t * Bsz + m) * Hh + j] = hn;
                }
            }
            gridsync(phase);
        }

        // ---- P2: q partials = h_t @ W12T[:, 0:512], K-split 8 (mac64) ----
        const int Kb = MHh / 8;
        const int tilesB = mt * 8 * 8;
        for (int tile = bid; tile < tilesB; tile += NB) {
            const int s  = tile & 7;
            const int u  = tile >> 3;
            const int n0 = (u & 7) << 6;
            const int m0 = (u >> 3) << 6;
            const int k0 = s * Kb;
            float* __restrict__ qout = g_qp[s];
            float acc[4][4] = {};
            auto af = [&](int ml, int kk) -> float { return hW[(m0 + ml) * Hh + k0 + kk]; };
            auto bf = [&](int kk, int nl) -> float {
                return g_W12T[(size_t)(k0 + kk) * 1024 + n0 + nl];
            };
            mac64(acc, Kb, af, bf, As, Bs);
#pragma unroll
            for (int i = 0; i < 4; ++i) {
                int m = m0 + ty * 4 + i;
#pragma unroll
                for (int j = 0; j < 4; ++j)
                    qout[m * MHh + n0 + tx * 4 + j] = acc[i][j];
            }
        }
        gridsync(phase);

        // ---- P3: p1 partials = tanh(sum q + b12) @ W2T1, K-split 4 (mac64) ----
        const int Kc = MHh / KSC;
        const int tilesC = mt * 2 * KSC;
        for (int tile = bid; tile < tilesC; tile += NB) {
            const int s  = tile % KSC;
            const int u  = tile / KSC;
            const int n0 = (u & 1) << 6;
            const int m0 = (u >> 1) << 6;
            const int k0 = s * Kc;
            float* __restrict__ rout = g_rp[s] + (size_t)t * Bsz * Oo;
            float acc[4][4] = {};
            auto af = [&](int ml, int kk) -> float {
                int k = k0 + kk;
                float v = g_b12[k];
#pragma unroll
                for (int s2 = 0; s2 < 8; ++s2) v += g_qp[s2][(m0 + ml) * MHh + k];
                return tanh_f(v);
            };
            auto bf = [&](int kk, int nl) -> float { return g_W2T1[(k0 + kk) * Oo + n0 + nl]; };
            mac64(acc, Kc, af, bf, As, Bs);
#pragma unroll
            for (int i = 0; i < 4; ++i) {
                int m = m0 + ty * 4 + i;
#pragma unroll
                for (int j = 0; j < 4; ++j)
                    rout[(size_t)m * Oo + n0 + tx * 4 + j] = acc[i][j];
            }
        }
        gridsync(phase);
    }
}

// ---------------- final stage ----------------
__global__ void offsets_kernel(const float* __restrict__ offW2, const float* __restrict__ offb2,
                               float* __restrict__ out_off, int Np) {
    int warp = (blockIdx.x * blockDim.x + threadIdx.x) >> 5;
    int lane = threadIdx.x & 31;
    if (warp >= Np) return;
    const float* row = g_buf + (size_t)warp * MHh;
    float s = 0.f;
#pragma unroll
    for (int k = lane; k < MHh; k += 32) s += row[k] * offW2[k];
#pragma unroll
    for (int o = 16; o; o >>= 1) s += __shfl_xor_sync(0xFFFFFFFFu, s, o);
    if (lane == 0) out_off[warp] = s + offb2[0];
}

__global__ void gather_out(const int* __restrict__ pack_idx, float* __restrict__ out, int Np) {
    int gid = blockIdx.x * blockDim.x + threadIdx.x;
    if (gid >= Np * Oo) return;
    int i = gid >> 7, o = gid & 127;
    size_t p = (size_t)pack_idx[i];
    float v1 = g_b2cat[o];
#pragma unroll
    for (int s = 0; s < KSC; ++s) v1 += g_rp[s][p * Oo + o];
    size_t NO = (size_t)Np * Oo;
    out[(size_t)i * Oo + o] = v1;                 // flat_p1
    out[2 * NO + Np + (size_t)i * Oo + o] = v1;   // flat_out (== flat_p1)
}

// ---------------- host ----------------
static float* gsymf(const void* symbol) {
    void* p = nullptr;
    cudaGetSymbolAddress(&p, symbol);
    return (float*)p;
}

extern "C" void kernel_launch(void* const* d_in, const int* in_sizes, int n_in,
                              void* d_out, int out_size) {
    const float* features = (const float*)d_in[0];
    const float* W_f2h    = (const float*)d_in[1];
    const float* b_f2h    = (const float*)d_in[2];
    const float* W_ih     = (const float*)d_in[3];
    const float* W_hh     = (const float*)d_in[4];
    const float* b_ih     = (const float*)d_in[5];
    const float* b_hh     = (const float*)d_in[6];
    const float* p1_W1    = (const float*)d_in[7];
    const float* p1_b1    = (const float*)d_in[8];
    const float* p1_W2    = (const float*)d_in[9];
    const float* p1_b2    = (const float*)d_in[10];
    const float* p2_W1    = (const float*)d_in[11];
    const float* p2_b1    = (const float*)d_in[12];
    const float* p2_W2    = (const float*)d_in[13];
    const float* p2_b2    = (const float*)d_in[14];
    const float* off_W1   = (const float*)d_in[15];
    const float* off_b1   = (const float*)d_in[16];
    const float* off_W2   = (const float*)d_in[17];
    const float* off_b2   = (const float*)d_in[18];
    const int*   lengths  = (const int*)d_in[19];
    const int*   pack_idx = (const int*)d_in[20];
    float* out = (float*)d_out;
    const int Np = in_sizes[20];
    const size_t NO = (size_t)Np * Oo;
    const unsigned mT = (unsigned)((Np + 127) / 128);

    float* p_Wf2hT  = gsymf(g_Wf2hT);
    float* p_bhc    = gsymf(g_bhc);
    float* p_W12T   = gsymf(g_W12T);
    float* p_b12    = gsymf(g_b12);
    float* p_W2T2   = gsymf(g_W2T2);
    float* p_b2cat  = gsymf(g_b2cat);
    float* p_offW1T = gsymf(g_offW1T);
    float* p_hs     = gsymf(g_hs);
    float* p_buf    = gsymf(g_buf);

    auto blocks = [](long long n) { return (unsigned)((n + 255) / 256); };

    // launch 1-2: prep ; launch 3: init GEMM ; launch 4: the scan
    k_prepA<<<blocks(4LL * Hh * Hh), 256>>>(W_ih, W_hh, b_ih, b_hh, W_f2h, b_f2h);
    k_prepB<<<blocks((long long)Hh * 2 * MHh), 256>>>(p1_W1, p2_W1, p1_b1, p2_b1,
                                                      p1_W2, p2_W2, p1_b2, p2_b2,
                                                      off_W1, lengths);
    gemmG<2><<<dim3(8, 2), TPB>>>(features, Ff, nullptr, p_Wf2hT, 2 * Hh, p_bhc,
                                  nullptr, Bsz, 2 * Hh, Ff);
    persistent_scan<<<NB, TPB>>>();

    // post-loop over packed rows
    gemmG<1><<<dim3(4, mT), TPB>>>(p_hs, Hh, pack_idx, p_offW1T, MHh, off_b1,
                                   p_buf, Np, MHh, Hh);
    offsets_kernel<<<(Np + 7) / 8, 256>>>(off_W2, off_b2, out + 2 * NO, Np);

    gemmG<1><<<dim3(4, mT), TPB>>>(p_hs, Hh, pack_idx, p_W12T + MHh, 2 * MHh, p_b12 + MHh,
                                   p_buf, Np, MHh, Hh);
    gemmG<0><<<dim3(1, mT), TPB>>>(p_buf, MHh, nullptr, p_W2T2, Oo, p_b2cat + Oo,
                                   out + NO, Np, Oo, MHh);

    gather_out<<<blocks((long long)Np * Oo), 256>>>(pack_idx, out, Np);
}